// round 3
// baseline (speedup 1.0000x reference)
#include <cuda_runtime.h>
#include <math.h>

#define NN 10000
#define EE 160000
#define HCDIM 256
#define CDIM 64

// ---------------- scratch (static device globals; no allocation) ----------------
__device__ float g_big0[(size_t)EE * HCDIM];   // h0 -> f
__device__ float g_big1[(size_t)EE * HCDIM];   // h1 -> then edge-MLP temps
__device__ float g_Xni[(size_t)NN * HCDIM];    // node @ W_ni  (x_j source)
__device__ float g_Xnj[(size_t)NN * HCDIM];    // node @ W_nj  (x_i source)
__device__ float g_P[(size_t)NN * HCDIM];      // Xnj @ A0[0:256]
__device__ float g_Q[(size_t)NN * HCDIM];      // Xni @ A0[512:768]
__device__ float g_agg[(size_t)NN * HCDIM];
__device__ float g_Wcomb[128 * HCDIM];         // W_eij @ A0[256:512]
__device__ float g_scores[(size_t)EE * 4];
__device__ float g_alpha[(size_t)EE * 4];
__device__ float g_smax[NN * 4];
__device__ float g_den[NN * 4];
__device__ float g_nA[NN * CDIM];
__device__ float g_nB[NN * CDIM];
__device__ float g_nC[NN * CDIM];
__device__ float g_nodeout[NN * CDIM];
__device__ float g_xg[NN * CDIM];
__device__ float g_deg[NN];
__device__ float g_dinv[NN];

// ---------------- generic tiled SGEMM with fused epilogue ----------------
// C[M,N] = A[M,K] @ B[K,N]   (all row-major)
// epilogue order: +bias, +gather0, +gather1, relu, +add0
// Requirements: N % 64 == 0, K % 16 == 0 (M arbitrary).
__global__ void gemm64(const float* __restrict__ A, const float* __restrict__ B,
                       float* __restrict__ C, int M, int N, int K,
                       const float* __restrict__ bias, int doRelu,
                       const float* __restrict__ add0,
                       const float* __restrict__ g0, const int* __restrict__ g0i,
                       const float* __restrict__ g1, const int* __restrict__ g1i)
{
    __shared__ float As[16][64];
    __shared__ float Bs[16][64];
    const int tid = threadIdx.x;
    const int bm = blockIdx.y * 64;
    const int bn = blockIdx.x * 64;
    const int ar = tid >> 2;         // 0..63  (row within A tile)
    const int ak = (tid & 3) << 2;   // 0,4,8,12
    const int bk = tid >> 4;         // 0..15  (k within B tile)
    const int bc = (tid & 15) << 2;  // col*4
    const int tx = tid & 15, ty = tid >> 4;

    float acc[4][4];
#pragma unroll
    for (int i = 0; i < 4; i++)
#pragma unroll
        for (int j = 0; j < 4; j++) acc[i][j] = 0.f;

    const int arow = bm + ar;
    const bool aok = arow < M;
    const float* Aptr = A + (size_t)arow * K + ak;
    const float* Bptr = B + (size_t)bk * N + bn + bc;

    for (int k0 = 0; k0 < K; k0 += 16) {
        float4 av = make_float4(0.f, 0.f, 0.f, 0.f);
        if (aok) av = *(const float4*)(Aptr + k0);
        As[ak + 0][ar] = av.x; As[ak + 1][ar] = av.y;
        As[ak + 2][ar] = av.z; As[ak + 3][ar] = av.w;
        *(float4*)(&Bs[bk][bc]) = *(const float4*)(Bptr + (size_t)k0 * N);
        __syncthreads();
#pragma unroll
        for (int k = 0; k < 16; k++) {
            float4 a = *(const float4*)(&As[k][ty * 4]);
            float4 b = *(const float4*)(&Bs[k][tx * 4]);
            acc[0][0] += a.x * b.x; acc[0][1] += a.x * b.y; acc[0][2] += a.x * b.z; acc[0][3] += a.x * b.w;
            acc[1][0] += a.y * b.x; acc[1][1] += a.y * b.y; acc[1][2] += a.y * b.z; acc[1][3] += a.y * b.w;
            acc[2][0] += a.z * b.x; acc[2][1] += a.z * b.y; acc[2][2] += a.z * b.z; acc[2][3] += a.z * b.w;
            acc[3][0] += a.w * b.x; acc[3][1] += a.w * b.y; acc[3][2] += a.w * b.z; acc[3][3] += a.w * b.w;
        }
        __syncthreads();
    }

    const int c0 = bn + tx * 4;
    float bv[4] = {0.f, 0.f, 0.f, 0.f};
    if (bias) { bv[0] = bias[c0]; bv[1] = bias[c0 + 1]; bv[2] = bias[c0 + 2]; bv[3] = bias[c0 + 3]; }
#pragma unroll
    for (int i = 0; i < 4; i++) {
        const int r = bm + ty * 4 + i;
        if (r >= M) continue;
        float v[4];
#pragma unroll
        for (int j = 0; j < 4; j++) v[j] = acc[i][j] + bv[j];
        if (g0) {
            const float* s = g0 + (size_t)g0i[r] * N + c0;
#pragma unroll
            for (int j = 0; j < 4; j++) v[j] += s[j];
        }
        if (g1) {
            const float* s = g1 + (size_t)g1i[r] * N + c0;
#pragma unroll
            for (int j = 0; j < 4; j++) v[j] += s[j];
        }
        if (doRelu) {
#pragma unroll
            for (int j = 0; j < 4; j++) v[j] = fmaxf(v[j], 0.f);
        }
        if (add0) {
            const float* s = add0 + (size_t)r * N + c0;
#pragma unroll
            for (int j = 0; j < 4; j++) v[j] += s[j];
        }
        *(float4*)(C + (size_t)r * N + c0) = make_float4(v[0], v[1], v[2], v[3]);
    }
}

// ---------------- small kernels ----------------
__global__ void init_bufs(float* smax, float* den, float* agg, float* deg)
{
    int i = blockIdx.x * blockDim.x + threadIdx.x;
    if (i < NN * 4) { smax[i] = __int_as_float(0xFF800000); den[i] = 0.f; }
    if (i < NN) deg[i] = 1.f;  // self-loop weight
    if (i < NN * HCDIM) agg[i] = 0.f;
}

__device__ __forceinline__ void atomicMaxF(float* addr, float v)
{
    if (v >= 0.f) atomicMax((int*)addr, __float_as_int(v));
    else          atomicMin((unsigned int*)addr, __float_as_uint(v));
}

// warp per edge: scores[e,h] = sum_c f[e,h,c]*attn[h,c]; segment max over dst
__global__ void scores_kernel(const float* __restrict__ f, const float* __restrict__ attn,
                              const int* __restrict__ dst,
                              float* __restrict__ scores, float* __restrict__ smax)
{
    const int lane = threadIdx.x & 31;
    const int gw = (blockIdx.x * blockDim.x + threadIdx.x) >> 5;
    const int nw = (gridDim.x * blockDim.x) >> 5;
    const int h = lane >> 3, w = lane & 7;
    const float4 a0 = *(const float4*)(attn + h * 64 + w * 8);
    const float4 a1 = *(const float4*)(attn + h * 64 + w * 8 + 4);
    for (int e = gw; e < EE; e += nw) {
        const float* fr = f + (size_t)e * HCDIM + h * 64 + w * 8;
        float4 f0 = *(const float4*)(fr);
        float4 f1 = *(const float4*)(fr + 4);
        float s = f0.x * a0.x + f0.y * a0.y + f0.z * a0.z + f0.w * a0.w
                + f1.x * a1.x + f1.y * a1.y + f1.z * a1.z + f1.w * a1.w;
        s += __shfl_xor_sync(0xffffffffu, s, 1);
        s += __shfl_xor_sync(0xffffffffu, s, 2);
        s += __shfl_xor_sync(0xffffffffu, s, 4);
        if (w == 0) {
            scores[e * 4 + h] = s;
            atomicMaxF(&smax[dst[e] * 4 + h], s);
        }
    }
}

__global__ void exp_den(const float* __restrict__ scores, const float* __restrict__ smax,
                        const int* __restrict__ dst,
                        float* __restrict__ alpha, float* __restrict__ den)
{
    int i = blockIdx.x * blockDim.x + threadIdx.x;
    if (i >= EE * 4) return;
    int e = i >> 2, h = i & 3;
    int d = dst[e];
    float ex = __expf(scores[i] - smax[d * 4 + h]);
    alpha[i] = ex;
    atomicAdd(&den[d * 4 + h], ex);
}

__global__ void alpha_norm(float* __restrict__ alpha, const float* __restrict__ den,
                           const int* __restrict__ dst)
{
    int i = blockIdx.x * blockDim.x + threadIdx.x;
    if (i >= EE * 4) return;
    int e = i >> 2, h = i & 3;
    alpha[i] = alpha[i] / den[dst[e] * 4 + h];
}

__global__ void attn_w(const float* __restrict__ alpha, const float* __restrict__ linW,
                       float* __restrict__ out)
{
    int e = blockIdx.x * blockDim.x + threadIdx.x;
    if (e >= EE) return;
    float4 al = *(const float4*)(alpha + (size_t)e * 4);
    out[e] = al.x * linW[0] + al.y * linW[1] + al.z * linW[2] + al.w * linW[3];
}

// agg[dst] += Xni[src] * alpha   (per head)
__global__ void agg_scatter(const float* __restrict__ alpha, const float* __restrict__ Xni,
                            const int* __restrict__ src, const int* __restrict__ dst,
                            float* __restrict__ agg)
{
    int i = blockIdx.x * blockDim.x + threadIdx.x;
    if (i >= EE * HCDIM) return;
    int e = i >> 8, c = i & 255, h = c >> 6;
    float a = alpha[e * 4 + h];
    atomicAdd(&agg[(size_t)dst[e] * HCDIM + c], Xni[(size_t)src[e] * HCDIM + c] * a);
}

__global__ void deg_kernel(const int* __restrict__ src, const int* __restrict__ dst,
                           float* __restrict__ deg)
{
    int e = blockIdx.x * blockDim.x + threadIdx.x;
    if (e >= EE) return;
    int s = src[e];
    if (s != dst[e]) atomicAdd(&deg[s], 1.f);
}

__global__ void dinv_kernel(const float* __restrict__ deg, float* __restrict__ dinv)
{
    int n = blockIdx.x * blockDim.x + threadIdx.x;
    if (n < NN) dinv[n] = rsqrtf(deg[n]);   // deg >= 1 always
}

__global__ void gcn_self(const float* __restrict__ xg, const float* __restrict__ dinv,
                         const float* __restrict__ gcnb, float* __restrict__ out)
{
    int i = blockIdx.x * blockDim.x + threadIdx.x;
    if (i >= NN * CDIM) return;
    int n = i >> 6, c = i & 63;
    float d = dinv[n];
    out[i] = d * d * xg[i] + gcnb[c];
}

__global__ void gcn_scatter(const float* __restrict__ xg, const float* __restrict__ dinv,
                            const int* __restrict__ src, const int* __restrict__ dst,
                            float* __restrict__ out)
{
    int i = blockIdx.x * blockDim.x + threadIdx.x;
    if (i >= EE * CDIM) return;
    int e = i >> 6, c = i & 63;
    int s = src[e], d = dst[e];
    if (s != d)
        atomicAdd(&out[(size_t)d * CDIM + c], dinv[s] * dinv[d] * xg[(size_t)s * CDIM + c]);
}

// ---------------- host side ----------------
static inline void gemm(const float* A, const float* B, float* C, int M, int N, int K,
                        const float* bias, int relu, const float* add0 = nullptr,
                        const float* g0 = nullptr, const int* g0i = nullptr,
                        const float* g1 = nullptr, const int* g1i = nullptr)
{
    dim3 grid(N / 64, (M + 63) / 64);
    gemm64<<<grid, 256>>>(A, B, C, M, N, K, bias, relu, add0, g0, g0i, g1, g1i);
}

extern "C" void kernel_launch(void* const* d_in, const int* in_sizes, int n_in,
                              void* d_out, int out_size)
{
    (void)in_sizes; (void)n_in; (void)out_size;
    const float* nf    = (const float*)d_in[0];   // [N,256]
    const float* ef    = (const float*)d_in[1];   // [E,128]
    const int*   eidx  = (const int*)  d_in[2];   // [2,E]
    const float* W_ni  = (const float*)d_in[3];
    const float* W_nj  = (const float*)d_in[4];
    const float* W_eij = (const float*)d_in[5];
    const float* W_nt  = (const float*)d_in[6];
    const float* b_nt  = (const float*)d_in[7];
    const float* W_et  = (const float*)d_in[8];
    const float* b_et  = (const float*)d_in[9];
    const float* A0_W  = (const float*)d_in[10];  // [768,256]
    const float* A0_b  = (const float*)d_in[11];
    const float* A1_W  = (const float*)d_in[12];
    const float* A1_b  = (const float*)d_in[13];
    const float* A2_W  = (const float*)d_in[14];
    const float* A2_b  = (const float*)d_in[15];
    const float* attnp = (const float*)d_in[16];  // [4,64]
    const float* Nm0_W = (const float*)d_in[17];
    const float* Nm0_b = (const float*)d_in[18];
    const float* Nm1_W = (const float*)d_in[19];
    const float* Nm1_b = (const float*)d_in[20];
    const float* Nm2_W = (const float*)d_in[21];
    const float* Nm2_b = (const float*)d_in[22];
    const float* Em0_W = (const float*)d_in[23];
    const float* Em0_b = (const float*)d_in[24];
    const float* Em1_W = (const float*)d_in[25];
    const float* Em1_b = (const float*)d_in[26];
    const float* Em2_W = (const float*)d_in[27];
    const float* Em2_b = (const float*)d_in[28];
    const float* lin_W = (const float*)d_in[29];  // [4]
    const float* gcn_W = (const float*)d_in[30];
    const float* gcn_b = (const float*)d_in[31];

    const int* src = eidx;
    const int* dst = eidx + EE;

    float *big0, *big1, *Xni, *Xnj, *P, *Q, *agg, *Wcomb, *scores, *alpha;
    float *smax, *den, *nA, *nB, *nC, *nodeout, *xg, *deg, *dinv;
    cudaGetSymbolAddress((void**)&big0, g_big0);
    cudaGetSymbolAddress((void**)&big1, g_big1);
    cudaGetSymbolAddress((void**)&Xni, g_Xni);
    cudaGetSymbolAddress((void**)&Xnj, g_Xnj);
    cudaGetSymbolAddress((void**)&P, g_P);
    cudaGetSymbolAddress((void**)&Q, g_Q);
    cudaGetSymbolAddress((void**)&agg, g_agg);
    cudaGetSymbolAddress((void**)&Wcomb, g_Wcomb);
    cudaGetSymbolAddress((void**)&scores, g_scores);
    cudaGetSymbolAddress((void**)&alpha, g_alpha);
    cudaGetSymbolAddress((void**)&smax, g_smax);
    cudaGetSymbolAddress((void**)&den, g_den);
    cudaGetSymbolAddress((void**)&nA, g_nA);
    cudaGetSymbolAddress((void**)&nB, g_nB);
    cudaGetSymbolAddress((void**)&nC, g_nC);
    cudaGetSymbolAddress((void**)&nodeout, g_nodeout);
    cudaGetSymbolAddress((void**)&xg, g_xg);
    cudaGetSymbolAddress((void**)&deg, g_deg);
    cudaGetSymbolAddress((void**)&dinv, g_dinv);

    float* out_gcn  = (float*)d_out;                                    // [N,64]
    float* out_edge = (float*)d_out + (size_t)NN * CDIM;                // [E,64]
    float* out_attw = (float*)d_out + (size_t)NN * CDIM + (size_t)EE * CDIM; // [E]

    // edge-MLP temporaries carved out of big1 (free after f is computed)
    float* e0   = big1;
    float* e1   = big1 + (size_t)EE * CDIM;
    float* ebuf = big1 + (size_t)EE * CDIM * 2;

    // ---- init ----
    init_bufs<<<(NN * HCDIM + 255) / 256, 256>>>(smax, den, agg, deg);

    // ---- node-level transforms ----
    gemm(nf, W_ni, Xni, NN, HCDIM, 256, nullptr, 0);
    gemm(nf, W_nj, Xnj, NN, HCDIM, 256, nullptr, 0);
    gemm(Xnj, A0_W,                P, NN, HCDIM, HCDIM, nullptr, 0);       // rows 0:256 (x_i block)
    gemm(Xni, A0_W + 512 * HCDIM,  Q, NN, HCDIM, HCDIM, nullptr, 0);       // rows 512:768 (x_j block)
    gemm(W_eij, A0_W + 256 * HCDIM, Wcomb, 128, HCDIM, HCDIM, nullptr, 0); // fold W_eij into A0 middle

    // ---- edge MLP (attention features) ----
    // h0 = relu(ef @ Wcomb + P[dst] + Q[src] + A0_b)
    gemm(ef, Wcomb, big0, EE, HCDIM, 128, A0_b, 1, nullptr, P, dst, Q, src);
    gemm(big0, A1_W, big1, EE, HCDIM, HCDIM, A1_b, 1);   // h1
    gemm(big1, A2_W, big0, EE, HCDIM, HCDIM, A2_b, 1);   // f  (leaky-relu after relu is identity)

    // ---- segment softmax ----
    scores_kernel<<<20000, 256>>>(big0, attnp, dst, scores, smax);
    exp_den<<<(EE * 4 + 255) / 256, 256>>>(scores, smax, dst, alpha, den);
    alpha_norm<<<(EE * 4 + 255) / 256, 256>>>(alpha, den, dst);
    attn_w<<<(EE + 255) / 256, 256>>>(alpha, lin_W, out_attw);

    // ---- message aggregation ----
    agg_scatter<<<(EE * HCDIM + 255) / 256, 256>>>(alpha, Xni, src, dst, agg);

    // ---- node output MLP + residual transform ----
    gemm(agg, Nm0_W, nA, NN, CDIM, HCDIM, Nm0_b, 1);
    gemm(nA, Nm1_W, nB, NN, CDIM, CDIM, Nm1_b, 1);
    gemm(nf, W_nt, nC, NN, CDIM, 256, b_nt, 0);
    gemm(nB, Nm2_W, nodeout, NN, CDIM, CDIM, Nm2_b, 1, nC);  // relu(...) + (nf@W_nt+b_nt)

    // ---- edge output MLP ----
    gemm(big0, Em0_W, e0, EE, CDIM, HCDIM, Em0_b, 1);
    gemm(e0, Em1_W, e1, EE, CDIM, CDIM, Em1_b, 1);
    gemm(ef, W_et, ebuf, EE, CDIM, 128, b_et, 0);
    gemm(e1, Em2_W, out_edge, EE, CDIM, CDIM, Em2_b, 1, ebuf);

    // ---- GCN ----
    deg_kernel<<<(EE + 255) / 256, 256>>>(src, dst, deg);
    dinv_kernel<<<(NN + 255) / 256, 256>>>(deg, dinv);
    gemm(nodeout, gcn_W, xg, NN, CDIM, CDIM, nullptr, 0);
    gcn_self<<<(NN * CDIM + 255) / 256, 256>>>(xg, dinv, gcn_b, out_gcn);
    gcn_scatter<<<(EE * CDIM + 255) / 256, 256>>>(xg, dinv, src, dst, out_gcn);
}

// round 4
// speedup vs baseline: 2.2147x; 2.2147x over previous
#include <cuda_runtime.h>
#include <math.h>
#include <stdint.h>

#define NN 10000
#define EE 160000
#define HCDIM 256
#define CDIM 64

// ---------------- scratch (static device globals; no allocation) ----------------
__device__ float g_big0[(size_t)EE * HCDIM];   // h0 -> f
__device__ float g_big1[(size_t)EE * HCDIM];   // h1 -> then edge-MLP temps
__device__ float g_Xni[(size_t)NN * HCDIM];    // node @ W_ni  (x_j source)
__device__ float g_Xnj[(size_t)NN * HCDIM];    // node @ W_nj  (x_i source)
__device__ float g_P[(size_t)NN * HCDIM];      // Xnj @ A0[0:256]
__device__ float g_Q[(size_t)NN * HCDIM];      // Xni @ A0[512:768]
__device__ float g_agg[(size_t)NN * HCDIM];
__device__ float g_Wcomb[128 * HCDIM];         // W_eij @ A0[256:512]
__device__ float g_scores[(size_t)EE * 4];
__device__ float g_alpha[(size_t)EE * 4];
__device__ float g_smax[NN * 4];
__device__ float g_den[NN * 4];
__device__ float g_nA[NN * CDIM];
__device__ float g_nB[NN * CDIM];
__device__ float g_nC[NN * CDIM];
__device__ float g_nodeout[NN * CDIM];
__device__ float g_xg[NN * CDIM];
__device__ float g_deg[NN];
__device__ float g_dinv[NN];

// ---------------- tf32 tensor-core GEMM with fused epilogue ----------------
// C[M,N] = A[M,K] @ B[K,N]  row-major.  N % 64 == 0, K % 32 == 0, M arbitrary.
// epilogue order: +bias, +g0[g0i[r]], +g1[g1i[r]], relu, +add0
//
// BM=128, BN=64, BK=32. 4 warps (128 thr), warp tile 64x32 = 4x4 m16n8k8 atoms.
// As[128][36], Bs[32][72]: pad strides make fragment LDS bank-conflict-free.
#define AST 36
#define BST 72
#define GSMEM ((2 * 128 * AST + 2 * 32 * BST) * 4)

__device__ __forceinline__ uint32_t f2tf32(float x)
{
    uint32_t r;
    asm("cvt.rna.tf32.f32 %0, %1;" : "=r"(r) : "f"(x));
    return r;
}

__global__ void __launch_bounds__(128) gemm_tc(
    const float* __restrict__ A, const float* __restrict__ B, float* __restrict__ C,
    int M, int N, int K,
    const float* __restrict__ bias, int doRelu, const float* __restrict__ add0,
    const float* __restrict__ g0, const int* __restrict__ g0i,
    const float* __restrict__ g1, const int* __restrict__ g1i)
{
    extern __shared__ float smem[];
    float* AsBase = smem;                  // [2][128][AST]
    float* BsBase = smem + 2 * 128 * AST;  // [2][32][BST]

    const int tid = threadIdx.x;
    const int lane = tid & 31;
    const int wid = tid >> 5;
    const int wm = wid & 1;        // 2 warp rows of 64
    const int wn = wid >> 1;       // 2 warp cols of 32
    const int bm = blockIdx.y * 128;
    const int bn = blockIdx.x * 64;

    float acc[4][4][4];
#pragma unroll
    for (int mt = 0; mt < 4; mt++)
#pragma unroll
        for (int nt = 0; nt < 4; nt++)
#pragma unroll
            for (int i = 0; i < 4; i++) acc[mt][nt][i] = 0.f;

    float4 ra[8];
    float4 rb[4];

    auto loadTile = [&](int k0) {
#pragma unroll
        for (int i = 0; i < 8; i++) {
            int idx = tid + i * 128;
            int r = idx >> 3, c4 = (idx & 7) * 4;
            int grow = bm + r;
            if (grow < M) ra[i] = *(const float4*)(A + (size_t)grow * K + k0 + c4);
            else          ra[i] = make_float4(0.f, 0.f, 0.f, 0.f);
        }
#pragma unroll
        for (int i = 0; i < 4; i++) {
            int idx = tid + i * 128;
            int kk = idx >> 4, c4 = (idx & 15) * 4;
            rb[i] = *(const float4*)(B + (size_t)(k0 + kk) * N + bn + c4);
        }
    };
    auto storeTile = [&](int buf) {
        float* a = AsBase + buf * 128 * AST;
        float* b = BsBase + buf * 32 * BST;
#pragma unroll
        for (int i = 0; i < 8; i++) {
            int idx = tid + i * 128;
            int r = idx >> 3, c4 = (idx & 7) * 4;
            uint4 v = make_uint4(f2tf32(ra[i].x), f2tf32(ra[i].y), f2tf32(ra[i].z), f2tf32(ra[i].w));
            *(uint4*)(a + r * AST + c4) = v;
        }
#pragma unroll
        for (int i = 0; i < 4; i++) {
            int idx = tid + i * 128;
            int kk = idx >> 4, c4 = (idx & 15) * 4;
            uint4 v = make_uint4(f2tf32(rb[i].x), f2tf32(rb[i].y), f2tf32(rb[i].z), f2tf32(rb[i].w));
            *(uint4*)(b + kk * BST + c4) = v;
        }
    };

    loadTile(0);
    storeTile(0);
    __syncthreads();

    const int ntiles = K >> 5;
    for (int t = 0; t < ntiles; t++) {
        if (t + 1 < ntiles) loadTile((t + 1) * 32);
        const float* a = AsBase + (t & 1) * 128 * AST;
        const float* b = BsBase + (t & 1) * 32 * BST;
#pragma unroll
        for (int ks = 0; ks < 4; ks++) {
            uint32_t af[4][4], bf[4][2];
#pragma unroll
            for (int mt = 0; mt < 4; mt++) {
                const float* p = a + (wm * 64 + mt * 16 + (lane >> 2)) * AST + ks * 8 + (lane & 3);
                af[mt][0] = __float_as_uint(p[0]);
                af[mt][1] = __float_as_uint(p[8 * AST]);
                af[mt][2] = __float_as_uint(p[4]);
                af[mt][3] = __float_as_uint(p[8 * AST + 4]);
            }
#pragma unroll
            for (int nt = 0; nt < 4; nt++) {
                const float* p = b + (ks * 8 + (lane & 3)) * BST + wn * 32 + nt * 8 + (lane >> 2);
                bf[nt][0] = __float_as_uint(p[0]);
                bf[nt][1] = __float_as_uint(p[4 * BST]);
            }
#pragma unroll
            for (int mt = 0; mt < 4; mt++)
#pragma unroll
                for (int nt = 0; nt < 4; nt++) {
                    asm volatile(
                        "mma.sync.aligned.m16n8k8.row.col.f32.tf32.tf32.f32 "
                        "{%0,%1,%2,%3}, {%4,%5,%6,%7}, {%8,%9}, {%0,%1,%2,%3};"
                        : "+f"(acc[mt][nt][0]), "+f"(acc[mt][nt][1]),
                          "+f"(acc[mt][nt][2]), "+f"(acc[mt][nt][3])
                        : "r"(af[mt][0]), "r"(af[mt][1]), "r"(af[mt][2]), "r"(af[mt][3]),
                          "r"(bf[nt][0]), "r"(bf[nt][1]));
                }
        }
        if (t + 1 < ntiles) {
            storeTile((t + 1) & 1);
            __syncthreads();
        }
    }

    // epilogue
#pragma unroll
    for (int mt = 0; mt < 4; mt++) {
        const int rbase = bm + wm * 64 + mt * 16 + (lane >> 2);
#pragma unroll
        for (int half = 0; half < 2; half++) {
            const int r = rbase + half * 8;
            if (r >= M) continue;
            const float* g0p = g0 ? g0 + (size_t)g0i[r] * N : nullptr;
            const float* g1p = g1 ? g1 + (size_t)g1i[r] * N : nullptr;
#pragma unroll
            for (int nt = 0; nt < 4; nt++) {
                const int c = bn + wn * 32 + nt * 8 + (lane & 3) * 2;
                float v0 = acc[mt][nt][half * 2 + 0];
                float v1 = acc[mt][nt][half * 2 + 1];
                if (bias) { v0 += bias[c]; v1 += bias[c + 1]; }
                if (g0p) { v0 += g0p[c]; v1 += g0p[c + 1]; }
                if (g1p) { v0 += g1p[c]; v1 += g1p[c + 1]; }
                if (doRelu) { v0 = fmaxf(v0, 0.f); v1 = fmaxf(v1, 0.f); }
                if (add0) {
                    v0 += add0[(size_t)r * N + c];
                    v1 += add0[(size_t)r * N + c + 1];
                }
                *(float2*)(C + (size_t)r * N + c) = make_float2(v0, v1);
            }
        }
    }
}

// ---------------- small kernels ----------------
__global__ void init_bufs(float* smax, float* den, float* agg, float* deg)
{
    int i = blockIdx.x * blockDim.x + threadIdx.x;
    if (i < NN * 4) { smax[i] = __int_as_float(0xFF800000); den[i] = 0.f; }
    if (i < NN) deg[i] = 1.f;  // self-loop weight
    if (i < NN * HCDIM) agg[i] = 0.f;
}

__device__ __forceinline__ void atomicMaxF(float* addr, float v)
{
    if (v >= 0.f) atomicMax((int*)addr, __float_as_int(v));
    else          atomicMin((unsigned int*)addr, __float_as_uint(v));
}

__global__ void scores_kernel(const float* __restrict__ f, const float* __restrict__ attn,
                              const int* __restrict__ dst,
                              float* __restrict__ scores, float* __restrict__ smax)
{
    const int lane = threadIdx.x & 31;
    const int gw = (blockIdx.x * blockDim.x + threadIdx.x) >> 5;
    const int nw = (gridDim.x * blockDim.x) >> 5;
    const int h = lane >> 3, w = lane & 7;
    const float4 a0 = *(const float4*)(attn + h * 64 + w * 8);
    const float4 a1 = *(const float4*)(attn + h * 64 + w * 8 + 4);
    for (int e = gw; e < EE; e += nw) {
        const float* fr = f + (size_t)e * HCDIM + h * 64 + w * 8;
        float4 f0 = *(const float4*)(fr);
        float4 f1 = *(const float4*)(fr + 4);
        float s = f0.x * a0.x + f0.y * a0.y + f0.z * a0.z + f0.w * a0.w
                + f1.x * a1.x + f1.y * a1.y + f1.z * a1.z + f1.w * a1.w;
        s += __shfl_xor_sync(0xffffffffu, s, 1);
        s += __shfl_xor_sync(0xffffffffu, s, 2);
        s += __shfl_xor_sync(0xffffffffu, s, 4);
        if (w == 0) {
            scores[e * 4 + h] = s;
            atomicMaxF(&smax[dst[e] * 4 + h], s);
        }
    }
}

__global__ void exp_den(const float* __restrict__ scores, const float* __restrict__ smax,
                        const int* __restrict__ dst,
                        float* __restrict__ alpha, float* __restrict__ den)
{
    int i = blockIdx.x * blockDim.x + threadIdx.x;
    if (i >= EE * 4) return;
    int e = i >> 2, h = i & 3;
    int d = dst[e];
    float ex = __expf(scores[i] - smax[d * 4 + h]);
    alpha[i] = ex;
    atomicAdd(&den[d * 4 + h], ex);
}

__global__ void alpha_norm(float* __restrict__ alpha, const float* __restrict__ den,
                           const int* __restrict__ dst)
{
    int i = blockIdx.x * blockDim.x + threadIdx.x;
    if (i >= EE * 4) return;
    int e = i >> 2, h = i & 3;
    alpha[i] = alpha[i] / den[dst[e] * 4 + h];
}

__global__ void attn_w(const float* __restrict__ alpha, const float* __restrict__ linW,
                       float* __restrict__ out)
{
    int e = blockIdx.x * blockDim.x + threadIdx.x;
    if (e >= EE) return;
    float4 al = *(const float4*)(alpha + (size_t)e * 4);
    out[e] = al.x * linW[0] + al.y * linW[1] + al.z * linW[2] + al.w * linW[3];
}

__global__ void agg_scatter(const float* __restrict__ alpha, const float* __restrict__ Xni,
                            const int* __restrict__ src, const int* __restrict__ dst,
                            float* __restrict__ agg)
{
    int i = blockIdx.x * blockDim.x + threadIdx.x;
    if (i >= EE * HCDIM) return;
    int e = i >> 8, c = i & 255, h = c >> 6;
    float a = alpha[e * 4 + h];
    atomicAdd(&agg[(size_t)dst[e] * HCDIM + c], Xni[(size_t)src[e] * HCDIM + c] * a);
}

__global__ void deg_kernel(const int* __restrict__ src, const int* __restrict__ dst,
                           float* __restrict__ deg)
{
    int e = blockIdx.x * blockDim.x + threadIdx.x;
    if (e >= EE) return;
    int s = src[e];
    if (s != dst[e]) atomicAdd(&deg[s], 1.f);
}

__global__ void dinv_kernel(const float* __restrict__ deg, float* __restrict__ dinv)
{
    int n = blockIdx.x * blockDim.x + threadIdx.x;
    if (n < NN) dinv[n] = rsqrtf(deg[n]);   // deg >= 1 always
}

__global__ void gcn_self(const float* __restrict__ xg, const float* __restrict__ dinv,
                         const float* __restrict__ gcnb, float* __restrict__ out)
{
    int i = blockIdx.x * blockDim.x + threadIdx.x;
    if (i >= NN * CDIM) return;
    int n = i >> 6, c = i & 63;
    float d = dinv[n];
    out[i] = d * d * xg[i] + gcnb[c];
}

__global__ void gcn_scatter(const float* __restrict__ xg, const float* __restrict__ dinv,
                            const int* __restrict__ src, const int* __restrict__ dst,
                            float* __restrict__ out)
{
    int i = blockIdx.x * blockDim.x + threadIdx.x;
    if (i >= EE * CDIM) return;
    int e = i >> 6, c = i & 63;
    int s = src[e], d = dst[e];
    if (s != d)
        atomicAdd(&out[(size_t)d * CDIM + c], dinv[s] * dinv[d] * xg[(size_t)s * CDIM + c]);
}

// ---------------- host side ----------------
static inline void gemm(const float* A, const float* B, float* C, int M, int N, int K,
                        const float* bias, int relu, const float* add0 = nullptr,
                        const float* g0 = nullptr, const int* g0i = nullptr,
                        const float* g1 = nullptr, const int* g1i = nullptr)
{
    dim3 grid(N / 64, (M + 127) / 128);
    gemm_tc<<<grid, 128, GSMEM>>>(A, B, C, M, N, K, bias, relu, add0, g0, g0i, g1, g1i);
}

extern "C" void kernel_launch(void* const* d_in, const int* in_sizes, int n_in,
                              void* d_out, int out_size)
{
    (void)in_sizes; (void)n_in; (void)out_size;
    const float* nf    = (const float*)d_in[0];   // [N,256]
    const float* ef    = (const float*)d_in[1];   // [E,128]
    const int*   eidx  = (const int*)  d_in[2];   // [2,E]
    const float* W_ni  = (const float*)d_in[3];
    const float* W_nj  = (const float*)d_in[4];
    const float* W_eij = (const float*)d_in[5];
    const float* W_nt  = (const float*)d_in[6];
    const float* b_nt  = (const float*)d_in[7];
    const float* W_et  = (const float*)d_in[8];
    const float* b_et  = (const float*)d_in[9];
    const float* A0_W  = (const float*)d_in[10];  // [768,256]
    const float* A0_b  = (const float*)d_in[11];
    const float* A1_W  = (const float*)d_in[12];
    const float* A1_b  = (const float*)d_in[13];
    const float* A2_W  = (const float*)d_in[14];
    const float* A2_b  = (const float*)d_in[15];
    const float* attnp = (const float*)d_in[16];  // [4,64]
    const float* Nm0_W = (const float*)d_in[17];
    const float* Nm0_b = (const float*)d_in[18];
    const float* Nm1_W = (const float*)d_in[19];
    const float* Nm1_b = (const float*)d_in[20];
    const float* Nm2_W = (const float*)d_in[21];
    const float* Nm2_b = (const float*)d_in[22];
    const float* Em0_W = (const float*)d_in[23];
    const float* Em0_b = (const float*)d_in[24];
    const float* Em1_W = (const float*)d_in[25];
    const float* Em1_b = (const float*)d_in[26];
    const float* Em2_W = (const float*)d_in[27];
    const float* Em2_b = (const float*)d_in[28];
    const float* lin_W = (const float*)d_in[29];  // [4]
    const float* gcn_W = (const float*)d_in[30];
    const float* gcn_b = (const float*)d_in[31];

    const int* src = eidx;
    const int* dst = eidx + EE;

    float *big0, *big1, *Xni, *Xnj, *P, *Q, *agg, *Wcomb, *scores, *alpha;
    float *smax, *den, *nA, *nB, *nC, *nodeout, *xg, *deg, *dinv;
    cudaGetSymbolAddress((void**)&big0, g_big0);
    cudaGetSymbolAddress((void**)&big1, g_big1);
    cudaGetSymbolAddress((void**)&Xni, g_Xni);
    cudaGetSymbolAddress((void**)&Xnj, g_Xnj);
    cudaGetSymbolAddress((void**)&P, g_P);
    cudaGetSymbolAddress((void**)&Q, g_Q);
    cudaGetSymbolAddress((void**)&agg, g_agg);
    cudaGetSymbolAddress((void**)&Wcomb, g_Wcomb);
    cudaGetSymbolAddress((void**)&scores, g_scores);
    cudaGetSymbolAddress((void**)&alpha, g_alpha);
    cudaGetSymbolAddress((void**)&smax, g_smax);
    cudaGetSymbolAddress((void**)&den, g_den);
    cudaGetSymbolAddress((void**)&nA, g_nA);
    cudaGetSymbolAddress((void**)&nB, g_nB);
    cudaGetSymbolAddress((void**)&nC, g_nC);
    cudaGetSymbolAddress((void**)&nodeout, g_nodeout);
    cudaGetSymbolAddress((void**)&xg, g_xg);
    cudaGetSymbolAddress((void**)&deg, g_deg);
    cudaGetSymbolAddress((void**)&dinv, g_dinv);

    cudaFuncSetAttribute(gemm_tc, cudaFuncAttributeMaxDynamicSharedMemorySize, GSMEM);

    float* out_gcn  = (float*)d_out;                                         // [N,64]
    float* out_edge = (float*)d_out + (size_t)NN * CDIM;                     // [E,64]
    float* out_attw = (float*)d_out + (size_t)NN * CDIM + (size_t)EE * CDIM; // [E]

    // edge-MLP temporaries carved out of big1 (free after f is computed)
    float* e0   = big1;
    float* e1   = big1 + (size_t)EE * CDIM;
    float* ebuf = big1 + (size_t)EE * CDIM * 2;

    // ---- init ----
    init_bufs<<<(NN * HCDIM + 255) / 256, 256>>>(smax, den, agg, deg);

    // ---- node-level transforms ----
    gemm(nf, W_ni, Xni, NN, HCDIM, 256, nullptr, 0);
    gemm(nf, W_nj, Xnj, NN, HCDIM, 256, nullptr, 0);
    gemm(Xnj, A0_W,                P, NN, HCDIM, HCDIM, nullptr, 0);       // rows 0:256 (x_i block)
    gemm(Xni, A0_W + 512 * HCDIM,  Q, NN, HCDIM, HCDIM, nullptr, 0);       // rows 512:768 (x_j block)
    gemm(W_eij, A0_W + 256 * HCDIM, Wcomb, 128, HCDIM, HCDIM, nullptr, 0); // fold W_eij into A0 middle

    // ---- edge MLP (attention features) ----
    gemm(ef, Wcomb, big0, EE, HCDIM, 128, A0_b, 1, nullptr, P, dst, Q, src);
    gemm(big0, A1_W, big1, EE, HCDIM, HCDIM, A1_b, 1);   // h1
    gemm(big1, A2_W, big0, EE, HCDIM, HCDIM, A2_b, 1);   // f  (leaky-relu after relu is identity)

    // ---- segment softmax ----
    scores_kernel<<<20000, 256>>>(big0, attnp, dst, scores, smax);
    exp_den<<<(EE * 4 + 255) / 256, 256>>>(scores, smax, dst, alpha, den);
    alpha_norm<<<(EE * 4 + 255) / 256, 256>>>(alpha, den, dst);
    attn_w<<<(EE + 255) / 256, 256>>>(alpha, lin_W, out_attw);

    // ---- message aggregation ----
    agg_scatter<<<(EE * HCDIM + 255) / 256, 256>>>(alpha, Xni, src, dst, agg);

    // ---- node output MLP + residual transform ----
    gemm(agg, Nm0_W, nA, NN, CDIM, HCDIM, Nm0_b, 1);
    gemm(nA, Nm1_W, nB, NN, CDIM, CDIM, Nm1_b, 1);
    gemm(nf, W_nt, nC, NN, CDIM, 256, b_nt, 0);
    gemm(nB, Nm2_W, nodeout, NN, CDIM, CDIM, Nm2_b, 1, nC);

    // ---- edge output MLP ----
    gemm(big0, Em0_W, e0, EE, CDIM, HCDIM, Em0_b, 1);
    gemm(e0, Em1_W, e1, EE, CDIM, CDIM, Em1_b, 1);
    gemm(ef, W_et, ebuf, EE, CDIM, 128, b_et, 0);
    gemm(e1, Em2_W, out_edge, EE, CDIM, CDIM, Em2_b, 1, ebuf);

    // ---- GCN ----
    deg_kernel<<<(EE + 255) / 256, 256>>>(src, dst, deg);
    dinv_kernel<<<(NN + 255) / 256, 256>>>(deg, dinv);
    gemm(nodeout, gcn_W, xg, NN, CDIM, CDIM, nullptr, 0);
    gcn_self<<<(NN * CDIM + 255) / 256, 256>>>(xg, dinv, gcn_b, out_gcn);
    gcn_scatter<<<(EE * CDIM + 255) / 256, 256>>>(xg, dinv, src, dst, out_gcn);
}